// round 17
// baseline (speedup 1.0000x reference)
#include <cuda_runtime.h>
#include <cuda_fp16.h>
#include <cstdint>
#include <cstddef>

#define T_LEN 16384
#define NTOT  131072
#define NBLK  16

#define DELTA 0.015625f     // 2^-6
#define C1    0.984375f     // 1 - 2^-6

// ---------------- activations, time-major ----------------
__device__ __align__(16) __half g_Xh[2][(size_t)NTOT * 128];
__device__ __align__(16) __half g_Xm[2][(size_t)NTOT * 128];
__device__ __align__(16) __half g_Zt[(size_t)NTOT * 1920];        // tight z: [n][16 layers x 120]
__device__ __align__(16) __half g_ShP[(size_t)NTOT * 256];
__device__ __align__(16) __half g_SmP[(size_t)NTOT * 256];

// weight blocks. FG: K=240 (tap1||tap0) = 15 chunks. skip: K=1920 tight, single plane.
__device__ __align__(16) __half g_WFG[(size_t)NBLK * 2 * 15 * 4096];
__device__ __align__(16) __half g_WRS[(size_t)NBLK * 8 * 4096];
__device__ __align__(16) __half g_WSK[(size_t)2 * 120 * 2048];
__device__ __align__(16) __half g_W1b[(size_t)2 * 15 * 4096];
__device__ __align__(16) __half g_W2b[(size_t)2 * 16 * 4096];
__device__ float g_Bsk[256];

// ---------------- helpers ----------------
__device__ __forceinline__ uint32_t smem_u32(const void* p) {
    uint32_t a;
    asm("{ .reg .u64 t; cvta.to.shared.u64 t, %1; cvt.u32.u64 %0, t; }" : "=r"(a) : "l"(p));
    return a;
}
__device__ __forceinline__ void msplit(float v, __half& h, __half& m) {
    h = __float2half(v);
    float hf = __half2float(h);
    m = __float2half(DELTA * hf + (v - hf));
}
__device__ __forceinline__ void wsplit(float v, __half& w1, __half& w2) {
    w1 = __float2half(C1 * v);
    float w1f = __half2float(w1);
    w2 = __float2half((v - w1f) * 64.0f);
}
__device__ __forceinline__ float gated_act(float f, float g) {
    float ef = __expf(-2.0f * fabsf(f));
    float eg = __expf(-g);
    float z = (1.0f - ef) * __fdividef(1.0f, (1.0f + ef) * (1.0f + eg));
    return copysignf(z, f);
}

// ---------------- packing ----------------
__global__ void pack_fg(const float* __restrict__ Wf, const float* __restrict__ Wg) {
    int idx = blockIdx.x * blockDim.x + threadIdx.x;     // NBLK*2*15*4096
    int kin = idx & 15, row = (idx >> 4) & 127;
    int blk = idx >> 11;
    int c = blk % 15, nt = (blk / 15) & 1, l = blk / 30;
    int m = nt * 128 + row, ch = m >> 1, isg = m & 1;
    int vch = c * 16 + kin;
    int tap = (vch < 120) ? 1 : 0;
    int cin = tap ? vch : vch - 120;
    float v = 0.f;
    if (ch < 120) {
        const float* s = isg ? Wg : Wf;
        v = s[(((size_t)l * 120 + ch) * 120 + cin) * 2 + tap];
    }
    __half h, mo; wsplit(v, h, mo);
    __half* b = g_WFG + ((size_t)((l * 2 + nt) * 15 + c)) * 4096;
    b[row * 16 + kin] = h;
    b[2048 + row * 16 + kin] = mo;
}

__global__ void pack_rs(const float* __restrict__ Wres) {
    int idx = blockIdx.x * blockDim.x + threadIdx.x;
    int kin = idx & 15, row = (idx >> 4) & 127, c = (idx >> 11) & 7, l = idx >> 14;
    int cin = c * 16 + kin;
    float v = (row < 120 && cin < 120) ? Wres[((size_t)l * 120 + row) * 120 + cin] : 0.f;
    __half h, mo; wsplit(v, h, mo);
    __half* blk = g_WRS + ((size_t)(l * 8 + c)) * 4096;
    blk[row * 16 + kin] = h;
    blk[2048 + row * 16 + kin] = mo;
}

// skip W: tight K = l*120 + cin, 120 chunks of 16, single fp16 plane
__global__ void pack_sk(const float* __restrict__ Wskip, const float* __restrict__ bskip) {
    int idx = blockIdx.x * blockDim.x + threadIdx.x;   // 2*120*2048
    int kin = idx & 15, row = (idx >> 4) & 127;
    int blk = idx >> 11;
    int cc = blk % 120, nt = blk / 120;
    int q = nt * 128 + row;
    int k = cc * 16 + kin, lay = k / 120, cin = k % 120;
    float v = (q < 240) ? Wskip[((size_t)lay * 240 + q) * 120 + cin] : 0.f;
    g_WSK[((size_t)(nt * 120 + cc)) * 2048 + row * 16 + kin] = __float2half(v);
    if (idx < 256) {
        float s = 0.f;
        if (idx < 240) for (int j = 0; j < NBLK; j++) s += bskip[j * 240 + idx];
        g_Bsk[idx] = s;
    }
}

__global__ void pack_h(const float* __restrict__ W1, const float* __restrict__ W2) {
    int idx = blockIdx.x * blockDim.x + threadIdx.x;   // 2*16*2048
    int kin = idx & 15, row = (idx >> 4) & 127, c = (idx >> 11) & 15, nt = idx >> 15;
    int q = nt * 128 + row, k = c * 16 + kin;
    __half h, mo;
    if (c < 15) {
        wsplit(W1[(size_t)q * 240 + k], h, mo);
        __half* b1 = g_W1b + ((size_t)(nt * 15 + c)) * 4096;
        b1[row * 16 + kin] = h; b1[2048 + row * 16 + kin] = mo;
    }
    wsplit(W2[(size_t)q * 256 + k], h, mo);
    __half* b2 = g_W2b + ((size_t)(nt * 16 + c)) * 4096;
    b2[row * 16 + kin] = h; b2[2048 + row * 16 + kin] = mo;
}

__global__ void init_kernel(const float* __restrict__ wave,
                            const float* __restrict__ W_in,
                            const float* __restrict__ b_in) {
    int idx = blockIdx.x * blockDim.x + threadIdx.x;
    int n = idx >> 7, c = idx & 127;
    float x = (c < 120) ? (W_in[c] * wave[n] + b_in[c]) : 0.f;
    __half h, m; msplit(x, h, m);
    g_Xh[0][idx] = h; g_Xm[0][idx] = m;
}

// ---------------- asm macros ----------------
#define CPA16(dst, src, sz) \
    asm volatile("cp.async.cg.shared.global [%0], [%1], 16, %2;" \
                 :: "r"(dst), "l"(src), "r"(sz) : "memory")
#define CPA8(dst, src) \
    asm volatile("cp.async.ca.shared.global [%0], [%1], 8;" \
                 :: "r"(dst), "l"(src) : "memory")
#define CP_COMMIT() asm volatile("cp.async.commit_group;" ::: "memory")
#define CP_WAIT2()  asm volatile("cp.async.wait_group 2;" ::: "memory")

#define LDM4(rr, addr) \
    asm volatile("ldmatrix.sync.aligned.m8n8.x4.shared.b16 {%0,%1,%2,%3}, [%4];" \
                 : "=r"((rr)[0]), "=r"((rr)[1]), "=r"((rr)[2]), "=r"((rr)[3]) : "r"(addr))

#define MMA(cr, a, b0v, b1v) \
    asm volatile("mma.sync.aligned.m16n8k16.row.col.f32.f16.f16.f32 " \
                 "{%0,%1,%2,%3}, {%4,%5,%6,%7}, {%8,%9}, {%0,%1,%2,%3};" \
                 : "+f"((cr)[0]), "+f"((cr)[1]), "+f"((cr)[2]), "+f"((cr)[3]) \
                 : "r"((a)[0]), "r"((a)[1]), "r"((a)[2]), "r"((a)[3]), "r"(b0v), "r"(b1v))

// ---------------- fused FG + RES kernel: CTA 128(time) x 256(col), 512 thr, 4 stages ----------------
#define SLOT  36864u
#define ZOFF  147456u
#define ZPIT  272u
#define ZPL   34816u
#define FS_BYTES (147456 + 2 * 34816)   // 217088

__global__ void __launch_bounds__(512, 1) fgres_kernel(int layer, int dil,
        const float* __restrict__ bf, const float* __restrict__ bg,
        const float* __restrict__ bres) {
    extern __shared__ __align__(16) char sm[];
    const int tid = threadIdx.x, lane = tid & 31, wid = tid >> 5;
    const int wn = wid >> 3, wc = wid & 7;
    const int n0 = blockIdx.x * 128;
    const uint32_t smb = smem_u32(sm);

    const __half* Xrh = g_Xh[layer & 1];
    const __half* Xrm = g_Xm[layer & 1];
    __half* Xwh = g_Xh[(layer + 1) & 1];
    __half* Xwm = g_Xm[(layer + 1) & 1];
    const __half* Wb  = g_WFG + (size_t)layer * 2 * 15 * 4096;
    const __half* WRb = g_WRS + (size_t)layer * 8 * 4096;

    uint32_t offA[4], offB[2], offRB;
    {
        int rA = wn * 64 + (lane & 15);
        int cA = (lane >> 4) * 16;
#pragma unroll
        for (int i = 0; i < 4; i++) offA[i] = (uint32_t)((rA + i * 16) * 48 + cA);
        int rB = wc * 32 + (lane >> 4) * 8 + (lane & 7);
        int cB = ((lane >> 3) & 1) * 16;
        offB[0] = (uint32_t)(rB * 48 + cB);
        offB[1] = (uint32_t)((rB + 16) * 48 + cB);
        int rR = wc * 16 + (lane >> 4) * 8 + (lane & 7);
        offRB = (uint32_t)(rR * 48 + cB);
    }

    float acc[4][4][4];
#pragma unroll
    for (int i = 0; i < 4; i++)
#pragma unroll
        for (int j = 0; j < 4; j++)
#pragma unroll
            for (int k = 0; k < 4; k++) acc[i][j][k] = 0.f;

#define FSTAGE(cc, s) do {                                                        \
        {                                                                         \
            int p = tid >> 8, r = (tid >> 1) & 127, hh = tid & 1;                 \
            int na = n0 + r, nn = na, sz = 16;                                    \
            int vch0 = (cc) * 16 + hh * 8, ch0 = vch0;                            \
            if (vch0 >= 120) {                                                    \
                ch0 = vch0 - 120;                                                 \
                int t = na & (T_LEN - 1);                                         \
                if (t >= dil) nn = na - dil; else sz = 0;                         \
            }                                                                     \
            uint32_t d = smb + (s) * SLOT + p * 6144u + r * 48u + hh * 16u;       \
            const __half* gp = (p ? Xrm : Xrh) + (size_t)nn * 128 + ch0;          \
            CPA16(d, gp, sz);                                                     \
        }                                                                         \
        _Pragma("unroll")                                                         \
        for (int ii = 0; ii < 2; ii++) {                                          \
            int u = tid + ii * 512, p = (u >> 9) & 1, r = (u >> 1) & 255, hh = u & 1; \
            uint32_t d = smb + (s) * SLOT + 12288u + p * 12288u + r * 48u + hh * 16u; \
            const __half* sp = Wb + ((size_t)((r >> 7) * 15 + (cc))) * 4096       \
                               + p * 2048 + (r & 127) * 16 + hh * 8;              \
            CPA16(d, sp, 16);                                                     \
        }                                                                         \
    } while (0)

    FSTAGE(0, 0); CP_COMMIT();
    FSTAGE(1, 1); CP_COMMIT();
    FSTAGE(2, 2); CP_COMMIT();

#pragma unroll 1
    for (int c = 0; c < 15; c++) {
        CP_WAIT2();
        __syncthreads();
        if (c + 3 < 15) FSTAGE(c + 3, (c + 3) & 3);
        CP_COMMIT();

        const uint32_t base = smb + (uint32_t)(c & 3) * SLOT;
        uint32_t A1[4][4], A2[4][4], Bf[2][4];
#pragma unroll
        for (int i = 0; i < 4; i++) {
            LDM4(A1[i], base + offA[i]);
            LDM4(A2[i], base + 6144u + offA[i]);
        }
        LDM4(Bf[0], base + 12288u + offB[0]);
        LDM4(Bf[1], base + 12288u + offB[1]);
#pragma unroll
        for (int i = 0; i < 4; i++)
#pragma unroll
            for (int j = 0; j < 4; j++)
                MMA(acc[i][j], A1[i], Bf[j >> 1][(j & 1) * 2], Bf[j >> 1][(j & 1) * 2 + 1]);
        LDM4(Bf[0], base + 24576u + offB[0]);
        LDM4(Bf[1], base + 24576u + offB[1]);
#pragma unroll
        for (int i = 0; i < 4; i++)
#pragma unroll
            for (int j = 0; j < 4; j++)
                MMA(acc[i][j], A2[i], Bf[j >> 1][(j & 1) * 2], Bf[j >> 1][(j & 1) * 2 + 1]);
    }
#undef FSTAGE

#define RSTAGE2(rc2, s) do {                                                      \
        _Pragma("unroll")                                                         \
        for (int sub = 0; sub < 2; sub++) {                                       \
            int rc = 2 * (rc2) + sub;                                             \
            int p = tid >> 8, r = (tid >> 1) & 127, hh = tid & 1;                 \
            uint32_t d = smb + (s) * SLOT + sub * 12288u + p * 6144u + r * 48u + hh * 16u; \
            const __half* sp = WRb + (size_t)rc * 4096 + p * 2048 + r * 16 + hh * 8; \
            CPA16(d, sp, 16);                                                     \
        }                                                                         \
    } while (0)

    __syncthreads();
    RSTAGE2(0, 0); CP_COMMIT();
    RSTAGE2(1, 1); CP_COMMIT();
    RSTAGE2(2, 2); CP_COMMIT();

    // ---- epilogue 1: z 2-plane into SMEM ----
#pragma unroll
    for (int j = 0; j < 4; j++) {
        int c0 = wc * 32 + j * 8 + (lane & 3) * 2;
        int ch = c0 >> 1;
        float bfv = 0.f, bgv = 0.f;
        if (ch < 120) { bfv = bf[layer * 120 + ch]; bgv = bg[layer * 120 + ch]; }
#pragma unroll
        for (int i = 0; i < 4; i++)
#pragma unroll
            for (int h = 0; h < 2; h++) {
                int row = wn * 64 + i * 16 + h * 8 + (lane >> 2);
                float z = gated_act(acc[i][j][h * 2] + bfv, acc[i][j][h * 2 + 1] + bgv);
                __half zh, zm; msplit(z, zh, zm);
                *reinterpret_cast<__half*>(sm + ZOFF + row * ZPIT + ch * 2) = zh;
                *reinterpret_cast<__half*>(sm + ZOFF + ZPL + row * ZPIT + ch * 2) = zm;
            }
    }

    __syncthreads();
    // ---- coalesced z -> g_Zt (tight layout), 16B stores ----
    {
        __half* zg = g_Zt + (size_t)n0 * 1920 + (size_t)layer * 120;
#pragma unroll
        for (int i = 0; i < 4; i++) {
            int u = tid + i * 512;              // 1920 units of 16B (15 per row)
            if (u < 1920) {
                int row = u / 15, o16 = u % 15;
                uint4 v = *reinterpret_cast<const uint4*>(sm + ZOFF + row * ZPIT + o16 * 16);
                *reinterpret_cast<uint4*>(zg + (size_t)row * 1920 + o16 * 8) = v;
            }
        }
    }

    // ---- RES GEMM ----
    float racc[4][2][4];
#pragma unroll
    for (int i = 0; i < 4; i++)
#pragma unroll
        for (int j = 0; j < 2; j++)
#pragma unroll
            for (int k = 0; k < 4; k++) racc[i][j][k] = 0.f;

#pragma unroll 1
    for (int rc2 = 0; rc2 < 4; rc2++) {
        CP_WAIT2();
        __syncthreads();
        if (rc2 + 3 < 4) RSTAGE2(rc2 + 3, (rc2 + 3) & 3);
        CP_COMMIT();

        const uint32_t base = smb + (uint32_t)(rc2 & 3) * SLOT;
#pragma unroll
        for (int sub = 0; sub < 2; sub++) {
            int rc = 2 * rc2 + sub;
            const uint32_t sb = base + (uint32_t)sub * 12288u;
            uint32_t Z1[4][4], Z2[4][4], RB[4];
            uint32_t zk = (uint32_t)(rc * 32) + (lane >> 4) * 16;
#pragma unroll
            for (int i = 0; i < 4; i++) {
                uint32_t zr = smb + ZOFF + (wn * 64 + i * 16 + (lane & 15)) * ZPIT + zk;
                LDM4(Z1[i], zr);
                LDM4(Z2[i], zr + ZPL);
            }
            LDM4(RB, sb + offRB);
#pragma unroll
            for (int i = 0; i < 4; i++)
#pragma unroll
                for (int j = 0; j < 2; j++)
                    MMA(racc[i][j], Z1[i], RB[j * 2], RB[j * 2 + 1]);
            LDM4(RB, sb + 6144u + offRB);
#pragma unroll
            for (int i = 0; i < 4; i++)
#pragma unroll
                for (int j = 0; j < 2; j++)
                    MMA(racc[i][j], Z2[i], RB[j * 2], RB[j * 2 + 1]);
        }
    }
#undef RSTAGE2

    // ---- epilogue 2: X_next ----
#pragma unroll
    for (int j = 0; j < 2; j++) {
        int col = wc * 16 + j * 8 + (lane & 3) * 2;
        if (col < 120) {
            float bv0 = bres[layer * 120 + col];
            float bv1 = bres[layer * 120 + col + 1];
#pragma unroll
            for (int i = 0; i < 4; i++)
#pragma unroll
                for (int h = 0; h < 2; h++) {
                    int row = n0 + wn * 64 + i * 16 + h * 8 + (lane >> 2);
                    size_t off = (size_t)row * 128 + col;
                    __half2 xh = *reinterpret_cast<const __half2*>(Xrh + off);
                    __half2 xm = *reinterpret_cast<const __half2*>(Xrm + off);
                    float x0 = C1 * __half2float(xh.x) + __half2float(xm.x)
                             + racc[i][j][h * 2] + bv0;
                    float x1 = C1 * __half2float(xh.y) + __half2float(xm.y)
                             + racc[i][j][h * 2 + 1] + bv1;
                    __half h0, m0, h1, m1;
                    msplit(x0, h0, m0); msplit(x1, h1, m1);
                    __half2 hp; hp.x = h0; hp.y = h1;
                    __half2 mp; mp.x = m0; mp.y = m1;
                    *reinterpret_cast<__half2*>(Xwh + off) = hp;
                    *reinterpret_cast<__half2*>(Xwm + off) = mp;
                }
        }
    }
}

// ---------------- skip kernel: CTA 128 x 256, K=1920 tight (60 iters x 2 chunks) ----------------
__global__ void __launch_bounds__(512, 1) skip_kernel(float* __restrict__ dummy) {
    extern __shared__ __align__(16) char sm[];
    const int tid = threadIdx.x, lane = tid & 31, wid = tid >> 5;
    const int wn = wid >> 3, wc = wid & 7;
    const int n0 = blockIdx.x * 128;
    const uint32_t smb = smem_u32(sm);

    uint32_t offA[4], offB[2];
    {
        int rA = wn * 64 + (lane & 15);
        int cA = (lane >> 4) * 16;
#pragma unroll
        for (int i = 0; i < 4; i++) offA[i] = (uint32_t)((rA + i * 16) * 48 + cA);
        int rB = wc * 32 + (lane >> 4) * 8 + (lane & 7);
        int cB = ((lane >> 3) & 1) * 16;
        offB[0] = (uint32_t)(rB * 48 + cB);
        offB[1] = (uint32_t)((rB + 16) * 48 + cB);
    }

    float acc[4][4][4];
#pragma unroll
    for (int i = 0; i < 4; i++)
#pragma unroll
        for (int j = 0; j < 4; j++)
#pragma unroll
            for (int k = 0; k < 4; k++) acc[i][j][k] = 0.f;

#define SSTAGE(it, s) do {                                                        \
        _Pragma("unroll")                                                         \
        for (int sub = 0; sub < 2; sub++) {                                       \
            int cc = 2 * (it) + sub;                                              \
            uint32_t rb = smb + (s) * 36864u + sub * 18432u;                      \
            {                                                                     \
                int r = tid >> 2, q = tid & 3;                                    \
                CPA8(rb + r * 48u + q * 8u,                                       \
                     g_Zt + (size_t)(n0 + r) * 1920 + cc * 16 + q * 4);           \
            }                                                                     \
            {                                                                     \
                int r = (tid >> 1) & 255, hh = tid & 1;                           \
                const __half* sp = g_WSK + ((size_t)((r >> 7) * 120 + cc)) * 2048 \
                                   + (r & 127) * 16 + hh * 8;                     \
                CPA16(rb + 6144u + r * 48u + hh * 16u, sp, 16);                   \
            }                                                                     \
        }                                                                         \
    } while (0)

    SSTAGE(0, 0); CP_COMMIT();
    SSTAGE(1, 1); CP_COMMIT();
    SSTAGE(2, 2); CP_COMMIT();

#pragma unroll 1
    for (int c = 0; c < 60; c++) {
        CP_WAIT2();
        __syncthreads();
        if (c + 3 < 60) SSTAGE(c + 3, (c + 3) & 3);
        CP_COMMIT();

        const uint32_t base = smb + (uint32_t)(c & 3) * 36864u;
#pragma unroll
        for (int sub = 0; sub < 2; sub++) {
            const uint32_t sb = base + (uint32_t)sub * 18432u;
            uint32_t Af[4][4], Bf[2][4];
#pragma unroll
            for (int i = 0; i < 4; i++) LDM4(Af[i], sb + offA[i]);
            LDM4(Bf[0], sb + 6144u + offB[0]);
            LDM4(Bf[1], sb + 6144u + offB[1]);
#pragma unroll
            for (int i = 0; i < 4; i++)
#pragma unroll
                for (int j = 0; j < 4; j++)
                    MMA(acc[i][j], Af[i], Bf[j >> 1][(j & 1) * 2], Bf[j >> 1][(j & 1) * 2 + 1]);
        }
    }
#undef SSTAGE

#pragma unroll
    for (int j = 0; j < 4; j++) {
        const int col = wc * 32 + j * 8 + (lane & 3) * 2;
        float bv0 = g_Bsk[col], bv1 = g_Bsk[col + 1];
#pragma unroll
        for (int i = 0; i < 4; i++)
#pragma unroll
            for (int h = 0; h < 2; h++) {
                int na = n0 + wn * 64 + i * 16 + h * 8 + (lane >> 2);
                float r0 = fmaxf(acc[i][j][h * 2] + bv0, 0.f);
                float r1 = fmaxf(acc[i][j][h * 2 + 1] + bv1, 0.f);
                __half h0, m0, h1, m1;
                msplit(r0, h0, m0); msplit(r1, h1, m1);
                __half2 hp; hp.x = h0; hp.y = h1;
                __half2 mp; mp.x = m0; mp.y = m1;
                *reinterpret_cast<__half2*>(g_ShP + (size_t)na * 256 + col) = hp;
                *reinterpret_cast<__half2*>(g_SmP + (size_t)na * 256 + col) = mp;
            }
    }
}

// ---------------- fused heads kernel: CTA 64(time) x 256, H tile in SMEM ----------------
// Stage slot (30720B): A@0 (2 planes x 64 x 48 = 6144) W@6144 (2 planes x 12288).
// H tile: 2 planes @ 122880, pitch 528, plane size 33792.
#define HSLOT 30720u
#define HOFF  122880u
#define HPIT  528u
#define HPL   33792u
#define HD_BYTES (122880 + 2 * 33792)   // 190464

__global__ void __launch_bounds__(512, 1) heads_kernel(const float* __restrict__ b1,
                                                       const float* __restrict__ b2,
                                                       float* __restrict__ dout) {
    extern __shared__ __align__(16) char sm[];
    const int tid = threadIdx.x, lane = tid & 31, wid = tid >> 5;
    const int wn = wid >> 3, wc = wid & 7;      // 2 time-groups(32) x 8 col-groups(32)
    const int n0 = blockIdx.x * 64;
    const uint32_t smb = smem_u32(sm);

    uint32_t offA[2], offB[2];
    {
        int rA = wn * 32 + (lane & 15);
        int cA = (lane >> 4) * 16;
        offA[0] = (uint32_t)(rA * 48 + cA);
        offA[1] = offA[0] + 16 * 48;
        int rB = wc * 32 + (lane >> 4) * 8 + (lane & 7);
        int cB = ((lane >> 3) & 1) * 16;
        offB[0] = (uint32_t)(rB * 48 + cB);
        offB[1] = (uint32_t)((rB + 16) * 48 + cB);
    }

    float acc[2][4][4];
#pragma unroll
    for (int i = 0; i < 2; i++)
#pragma unroll
        for (int j = 0; j < 4; j++)
#pragma unroll
            for (int k = 0; k < 4; k++) acc[i][j][k] = 0.f;

// phase 1: head1, A = S planes from gmem, W1 (15 chunks)
#define H1STAGE(cc, s) do {                                                       \
        if (tid < 256) {                                                          \
            int p = tid >> 7, r = (tid >> 1) & 63, hh = tid & 1;                  \
            const __half* ap = p ? g_SmP : g_ShP;                                 \
            uint32_t d = smb + (s) * HSLOT + p * 3072u + r * 48u + hh * 16u;      \
            CPA16(d, ap + (size_t)(n0 + r) * 256 + (cc) * 16 + hh * 8, 16);       \
        }                                                                         \
        _Pragma("unroll")                                                         \
        for (int ii = 0; ii < 2; ii++) {                                          \
            int u = tid + ii * 512, p = (u >> 9) & 1, r = (u >> 1) & 255, hh = u & 1; \
            uint32_t d = smb + (s) * HSLOT + 6144u + p * 12288u + r * 48u + hh * 16u; \
            const __half* sp = g_W1b + ((size_t)((r >> 7) * 15 + (cc))) * 4096    \
                               + p * 2048 + (r & 127) * 16 + hh * 8;              \
            CPA16(d, sp, 16);                                                     \
        }                                                                         \
    } while (0)

    H1STAGE(0, 0); CP_COMMIT();
    H1STAGE(1, 1); CP_COMMIT();
    H1STAGE(2, 2); CP_COMMIT();

#pragma unroll 1
    for (int c = 0; c < 15; c++) {
        CP_WAIT2();
        __syncthreads();
        if (c + 3 < 15) H1STAGE(c + 3, (c + 3) & 3);
        CP_COMMIT();

        const uint32_t base = smb + (uint32_t)(c & 3) * HSLOT;
        uint32_t A1[2][4], A2[2][4], Bf[2][4];
#pragma unroll
        for (int i = 0; i < 2; i++) {
            LDM4(A1[i], base + offA[i]);
            LDM4(A2[i], base + 3072u + offA[i]);
        }
        LDM4(Bf[0], base + 6144u + offB[0]);
        LDM4(Bf[1], base + 6144u + offB[1]);
#pragma unroll
        for (int i = 0; i < 2; i++)
#pragma unroll
            for (int j = 0; j < 4; j++)
                MMA(acc[i][j], A1[i], Bf[j >> 1][(j & 1) * 2], Bf[j >> 1][(j & 1) * 2 + 1]);
        LDM4(Bf[0], base + 18432u + offB[0]);
        LDM4(Bf[1], base + 18432u + offB[1]);
#pragma unroll
        for (int i = 0; i < 2; i++)
#pragma unroll
            for (int j = 0; j < 4; j++)
                MMA(acc[i][j], A2[i], Bf[j >> 1][(j & 1) * 2], Bf[j >> 1][(j & 1) * 2 + 1]);
    }
#undef H1STAGE

// phase 2 W2 prefetch (1 chunk per slot)
#define H2STAGE(cc, s) do {                                                       \
        _Pragma("unroll")                                                         \
        for (int ii = 0; ii < 2; ii++) {                                          \
            int u = tid + ii * 512, p = (u >> 9) & 1, r = (u >> 1) & 255, hh = u & 1; \
            uint32_t d = smb + (s) * HSLOT + p * 12288u + r * 48u + hh * 16u;     \
            const __half* sp = g_W2b + ((size_t)((r >> 7) * 16 + (cc))) * 4096    \
                               + p * 2048 + (r & 127) * 16 + hh * 8;              \
            CPA16(d, sp, 16);                                                     \
        }                                                                         \
    } while (0)

    __syncthreads();
    H2STAGE(0, 0); CP_COMMIT();
    H2STAGE(1, 1); CP_COMMIT();
    H2STAGE(2, 2); CP_COMMIT();

    // ---- H = relu(head1 + b1), 2-plane into SMEM H tile ----
#pragma unroll
    for (int j = 0; j < 4; j++) {
        int col = wc * 32 + j * 8 + (lane & 3) * 2;
        float bv0 = b1[col], bv1 = b1[col + 1];
#pragma unroll
        for (int i = 0; i < 2; i++)
#pragma unroll
            for (int h = 0; h < 2; h++) {
                int row = wn * 32 + i * 16 + h * 8 + (lane >> 2);
                float r0 = fmaxf(acc[i][j][h * 2] + bv0, 0.f);
                float r1 = fmaxf(acc[i][j][h * 2 + 1] + bv1, 0.f);
                __half h0, m0, h1, m1;
                msplit(r0, h0, m0); msplit(r1, h1, m1);
                __half2 hp; hp.x = h0; hp.y = h1;
                __half2 mp; mp.x = m0; mp.y = m1;
                *reinterpret_cast<__half2*>(sm + HOFF + row * HPIT + col * 2) = hp;
                *reinterpret_cast<__half2*>(sm + HOFF + HPL + row * HPIT + col * 2) = mp;
            }
    }

    // ---- head2: K=256 from SMEM H planes ----
    float acc2[2][4][4];
#pragma unroll
    for (int i = 0; i < 2; i++)
#pragma unroll
        for (int j = 0; j < 4; j++)
#pragma unroll
            for (int k = 0; k < 4; k++) acc2[i][j][k] = 0.f;

    __syncthreads();   // H tile complete (also orders W2 slot writes vs phase-1 reads done earlier)

#pragma unroll 1
    for (int c = 0; c < 16; c++) {
        CP_WAIT2();
        __syncthreads();
        if (c + 3 < 16) H2STAGE(c + 3, (c + 3) & 3);
        CP_COMMIT();

        const uint32_t base = smb + (uint32_t)(c & 3) * HSLOT;
        uint32_t Z1[2][4], Z2[2][4], Bf[2][4];
        uint32_t zk = (uint32_t)(c * 32) + (lane >> 4) * 16;
#pragma unroll
        for (int i = 0; i < 2; i++) {
            uint32_t zr = smb + HOFF + (wn * 32 + i * 16 + (lane & 15)) * HPIT + zk;
            LDM4(Z1[i], zr);
            LDM4(Z2[i], zr + HPL);
        }
        LDM4(Bf[0], base + offB[0]);
        LDM4(Bf[1], base + offB[1]);
#pragma unroll
        for (int i = 0; i < 2; i++)
#pragma unroll
            for (int j = 0; j < 4; j++)
                MMA(acc2[i][j], Z1[i], Bf[j >> 1][(j & 1) * 2], Bf[j >> 1][(j & 1) * 2 + 1]);
        LDM4(Bf[0], base + 12288u + offB[0]);
        LDM4(Bf[1], base + 12288u + offB[1]);
#pragma unroll
        for (int i = 0; i < 2; i++)
#pragma unroll
            for (int j = 0; j < 4; j++)
                MMA(acc2[i][j], Z2[i], Bf[j >> 1][(j & 1) * 2], Bf[j >> 1][(j & 1) * 2 + 1]);
    }
#undef H2STAGE

    // ---- logits ----
#pragma unroll
    for (int j = 0; j < 4; j++) {
        const int col = wc * 32 + j * 8 + (lane & 3) * 2;
        float bv0 = b2[col], bv1 = b2[col + 1];
#pragma unroll
        for (int i = 0; i < 2; i++)
#pragma unroll
            for (int h = 0; h < 2; h++) {
                int na = n0 + wn * 32 + i * 16 + h * 8 + (lane >> 2);
                int b = na >> 14, t = na & (T_LEN - 1);
                dout[((size_t)b * 256 + col) * T_LEN + t]     = acc2[i][j][h * 2] + bv0;
                dout[((size_t)b * 256 + col + 1) * T_LEN + t] = acc2[i][j][h * 2 + 1] + bv1;
            }
    }
}

// ---------------- launch ----------------
extern "C" void kernel_launch(void* const* d_in, const int* in_sizes, int n_in,
                              void* d_out, int out_size) {
    const float* wave  = (const float*)d_in[0];
    const float* W_in  = (const float*)d_in[1];
    const float* b_in  = (const float*)d_in[2];
    const float* Wf    = (const float*)d_in[3];
    const float* bf    = (const float*)d_in[4];
    const float* Wg    = (const float*)d_in[5];
    const float* bg    = (const float*)d_in[6];
    const float* Wres  = (const float*)d_in[7];
    const float* bres  = (const float*)d_in[8];
    const float* Wskip = (const float*)d_in[9];
    const float* bskip = (const float*)d_in[10];
    const float* W1    = (const float*)d_in[11];
    const float* b1    = (const float*)d_in[12];
    const float* W2    = (const float*)d_in[13];
    const float* b2    = (const float*)d_in[14];
    float* out = (float*)d_out;

    const int GS = 4 * 36864;
    cudaFuncSetAttribute(fgres_kernel, cudaFuncAttributeMaxDynamicSharedMemorySize, FS_BYTES);
    cudaFuncSetAttribute(skip_kernel,  cudaFuncAttributeMaxDynamicSharedMemorySize, GS);
    cudaFuncSetAttribute(heads_kernel, cudaFuncAttributeMaxDynamicSharedMemorySize, HD_BYTES);

    pack_fg<<<16 * 2 * 15 * 4096 / 256, 256>>>(Wf, Wg);
    pack_rs<<<16 * 8 * 2048 / 256, 256>>>(Wres);
    pack_sk<<<2 * 120 * 2048 / 256, 256>>>(Wskip, bskip);
    pack_h <<<2 * 16 * 2048 / 256, 256>>>(W1, W2);
    init_kernel<<<(size_t)NTOT * 128 / 256, 256>>>(wave, W_in, b_in);

    static const int dil[NBLK] = {1, 2, 4, 8, 16, 32, 64, 128,
                                  1, 2, 4, 8, 16, 32, 64, 128};

    for (int i = 0; i < NBLK; i++)
        fgres_kernel<<<NTOT / 128, 512, FS_BYTES>>>(i, dil[i], bf, bg, bres);

    skip_kernel <<<NTOT / 128, 512, GS>>>(nullptr);
    heads_kernel<<<NTOT / 64, 512, HD_BYTES>>>(b1, b2, out);
}